// round 11
// baseline (speedup 1.0000x reference)
#include <cuda_runtime.h>
#include <cuda_fp16.h>
#include <math.h>
#include <stdint.h>

#define N_SEL 200000
#define EVN   100000
#define MEMD  100
#define RAWD  172
#define NB    128
#define NBLK  ((N_SEL + NB - 1) / NB)
#define NTHR  512
#define KCH   9             // 9 K-chunks of 64 cols: [0,576), real K = 572
#define BROWS 408           // 400 weight rows + 8 zero pad

// ---- smem layout (bytes) ----
// A: fp16 [128 rows x 64 cols], row stride 144B (36 words), double buffered
// B: fp16 [408 rows x 64 cols], row stride 144B, TRIPLE buffered
#define A_BUF_SZ  18432
#define B_BUF_SZ  58752
#define A_OFF(i)  ((i) * A_BUF_SZ)
#define B_OFF(j)  (36864 + (j) * B_BUF_SZ)
#define GID_OFF   213120
#define DST_OFF   213632
#define IDX_OFF   214144
#define VAL_OFF   214656
#define TREL_OFF  215168
#define RAWP_OFF  215680
#define SMEM_TOTAL 216704

// ---------------- small PTX helpers ----------------
__device__ __forceinline__ uint32_t smem_u32(const void* p) {
    uint32_t a;
    asm("{ .reg .u64 t; cvta.to.shared.u64 t, %1; cvt.u32.u64 %0, t; }" : "=r"(a) : "l"(p));
    return a;
}
__device__ __forceinline__ uint32_t f16x2(float lo, float hi) {
    uint32_t d;
    asm("cvt.rn.f16x2.f32 %0, %1, %2;" : "=r"(d) : "f"(hi), "f"(lo));  // first src -> high half
    return d;
}
__device__ __forceinline__ void cp16(uint32_t dst, const void* src, uint32_t sz) {
    asm volatile("cp.async.cg.shared.global [%0], [%1], 16, %2;"
                 :: "r"(dst), "l"(src), "r"(sz) : "memory");
}
#define CP_COMMIT() asm volatile("cp.async.commit_group;" ::: "memory")
#define CP_WAIT1()  asm volatile("cp.async.wait_group 1;" ::: "memory")

__device__ __forceinline__ void mma16(float* c, const uint32_t* a, uint32_t b0, uint32_t b1) {
    asm volatile("mma.sync.aligned.m16n8k16.row.col.f32.f16.f16.f32 "
                 "{%0,%1,%2,%3}, {%4,%5,%6,%7}, {%8,%9}, {%0,%1,%2,%3};"
                 : "+f"(c[0]), "+f"(c[1]), "+f"(c[2]), "+f"(c[3])
                 : "r"(a[0]), "r"(a[1]), "r"(a[2]), "r"(a[3]), "r"(b0), "r"(b1));
}

// ---------------- device scratch ----------------
__device__ unsigned long long g_win[N_SEL];
__device__ int g_cnt_valid;
__device__ int g_cnt_invalid;
__device__ int g_list[N_SEL];
__device__ uint32_t g_Bpk[BROWS * 288];   // fp16x2 words: [408 rows][288 words], k16-permuted

// ---------------- aggregation ----------------
__global__ void k_init() {
    int i = blockIdx.x * blockDim.x + threadIdx.x;
    if (i < N_SEL) g_win[i] = 0ull;
    if (i == 0) { g_cnt_valid = 0; g_cnt_invalid = 0; }
}
__global__ void k_aggregate(const int* __restrict__ loc_s, const int* __restrict__ t_s,
                            const int* __restrict__ loc_d, const int* __restrict__ t_d) {
    int e = blockIdx.x * blockDim.x + threadIdx.x;
    if (e >= 2 * EVN) return;
    int loc, t;
    if (e < EVN) { loc = loc_s[e];       t = t_s[e]; }
    else         { loc = loc_d[e - EVN]; t = t_d[e - EVN]; }
    unsigned long long key = (((unsigned long long)(unsigned)(t + 1)) << 32) | (unsigned)e;
    atomicMax(&g_win[loc], key);
}
__global__ void k_partition() {
    int i = blockIdx.x * blockDim.x + threadIdx.x;
    if (i >= N_SEL) return;
    if (g_win[i] != 0ull) { int p = atomicAdd(&g_cnt_valid, 1);   g_list[p] = i; }
    else                  { int p = atomicAdd(&g_cnt_invalid, 1); g_list[N_SEL - 1 - p] = i; }
}

// ---------------- weight prepack: virtual B [408 x 576] -> fp16, k16-permuted ----------------
__device__ __forceinline__ float bval(int r, int c, const float* W_ih, const float* W_hh) {
    float v = 0.f;
    if (r < 200) {
        if (c < 472) v = __ldg(&W_ih[(size_t)r * 472 + c]);
        else if (c < 572) v = __ldg(&W_hh[(size_t)r * MEMD + (c - 472)]);
    } else if (r < 300) {
        if (c < 472) v = __ldg(&W_ih[(size_t)r * 472 + c]);
    } else if (r < 400) {
        if (c >= 472 && c < 572) v = __ldg(&W_hh[(size_t)(r - 100) * MEMD + (c - 472)]);
    }
    return v;
}
__global__ void k_prepack(const float* __restrict__ W_ih, const float* __restrict__ W_hh) {
    int idx = blockIdx.x * blockDim.x + threadIdx.x;
    if (idx >= BROWS * 288) return;
    int r = idx / 288, ow = idx - r * 288;
    int grp = ow >> 3, p = ow & 7;
    int sw = (p & 1) ? ((p >> 1) + 4) : (p >> 1);      // source word within k16 group
    int c0 = grp * 16 + sw * 2;
    __half2 hv = __floats2half2_rn(bval(r, c0, W_ih, W_hh), bval(r, c0 + 1, W_ih, W_hh));
    g_Bpk[idx] = *reinterpret_cast<uint32_t*>(&hv);
}

// ---------------- A staging: gather f32 -> cvt fp16 -> STS ----------------
__device__ __forceinline__ void stage_a(
    char* smem, int kc, int buf, int tid,
    const float* __restrict__ memory,
    const float* __restrict__ time_w, const float* __restrict__ time_b,
    const int* s_gid, const int* s_dst, const float* const* s_raw,
    const float* s_trel, const int* s_val)
{
    const int q  = tid & 15;
    const int c4 = kc * 64 + q * 4;
    char* Ab = smem + A_OFF(buf);
    #pragma unroll
    for (int pass = 0; pass < 4; pass++) {
        int m = (tid >> 4) + pass * 32;
        bool val = (s_val[m] != 0);
        float4 v = make_float4(0.f, 0.f, 0.f, 0.f);
        if (c4 >= 372 && c4 < 472) {
            if (val) {
                int col = c4 - 372;
                float tr = s_trel[m];
                float4 w = __ldg((const float4*)(time_w + col));
                float4 b = __ldg((const float4*)(time_b + col));
                v.x = cosf(fmaf(tr, w.x, b.x));
                v.y = cosf(fmaf(tr, w.y, b.y));
                v.z = cosf(fmaf(tr, w.z, b.z));
                v.w = cosf(fmaf(tr, w.w, b.w));
            }
        } else {
            const float4* src = nullptr;
            if (c4 < 100)      { if (val) src = (const float4*)(memory + (size_t)s_gid[m] * MEMD + c4); }
            else if (c4 < 200) { if (val) src = (const float4*)(memory + (size_t)s_dst[m] * MEMD + (c4 - 100)); }
            else if (c4 < 372) { if (val) src = (const float4*)(s_raw[m] + (c4 - 200)); }
            else if (c4 < 572) { src = (const float4*)(memory + (size_t)s_gid[m] * MEMD + (c4 - 472)); }
            if (src) v = __ldg(src);
        }
        uint2 w2;
        w2.x = f16x2(v.x, v.y);
        w2.y = f16x2(v.z, v.w);
        *(uint2*)(Ab + m * 144 + q * 8) = w2;   // word offset 2q (cols 4q..4q+3)
    }
}

// ---------------- B staging: dense cp.async from prepacked buffer ----------------
__device__ __forceinline__ void stage_b(uint32_t sm32, int kc, int buf, int tid) {
    const int q8 = tid & 7;
    const uint32_t* Bsrc = g_Bpk + kc * 32 + q8 * 4;
    uint32_t dst0 = sm32 + B_OFF(buf) + q8 * 16;
    for (int w = tid >> 3; w < BROWS; w += 64)
        cp16(dst0 + w * 144, Bsrc + (size_t)w * 288, 16);
}

// ---------------- per-chunk MMA: fp16 m16n8k16, both operands pre-fp16 ----------------
__device__ __forceinline__ void compute_chunk(
    const char* smem, int abuf, int bbuf, int wm, int wn, int g, int t,
    float (&acc)[2][13][4])
{
    const uint32_t* Aw = (const uint32_t*)(smem + A_OFF(abuf));
    const uint32_t* Bs = (const uint32_t*)(smem + B_OFF(bbuf)) + (wn * 100 + g) * 36 + 2 * t;
    #pragma unroll
    for (int ks = 0; ks < 4; ks++) {
        uint32_t a[2][4];
        #pragma unroll
        for (int mt = 0; mt < 2; mt++) {
            int base = (wm * 32 + mt * 16 + g) * 36 + ks * 8;
            a[mt][0] = Aw[base + t];
            a[mt][1] = Aw[base + 8 * 36 + t];
            a[mt][2] = Aw[base + t + 4];
            a[mt][3] = Aw[base + 8 * 36 + t + 4];
        }
        #pragma unroll
        for (int nt = 0; nt < 13; nt++) {
            uint2 b = *(const uint2*)(Bs + nt * 8 * 36 + ks * 8);
            mma16(acc[0][nt], a[0], b.x, b.y);
            mma16(acc[1][nt], a[1], b.x, b.y);
        }
    }
}

// ---------------- main fused kernel ----------------
__global__ __launch_bounds__(NTHR, 1)
void k_main3(const float* __restrict__ memory, const int* __restrict__ last_update,
             const int* __restrict__ n_id,
             const int* __restrict__ dst_s, const float* __restrict__ raw_s,
             const int* __restrict__ dst_d, const float* __restrict__ raw_d,
             const float* __restrict__ time_w, const float* __restrict__ time_b,
             const float* __restrict__ b_ih, const float* __restrict__ b_hh,
             float* __restrict__ out_mem, float* __restrict__ out_lu, int write_lu)
{
    extern __shared__ __align__(128) char smem[];
    const uint32_t sm32 = smem_u32(smem);
    const int tid  = threadIdx.x;
    const int lane = tid & 31;
    const int wid  = tid >> 5;
    const int g = lane >> 2, t = lane & 3;
    const int wn = wid & 3, wm = wid >> 2;
    const int base = blockIdx.x * NB;

    int*   s_gid  = (int*)(smem + GID_OFF);
    int*   s_dst  = (int*)(smem + DST_OFF);
    int*   s_idx  = (int*)(smem + IDX_OFF);
    int*   s_val  = (int*)(smem + VAL_OFF);
    float* s_trel = (float*)(smem + TREL_OFF);
    const float** s_raw = (const float**)(smem + RAWP_OFF);

    const int nValid = g_cnt_valid;

    // ---- prologue: per-node metadata ----
    if (tid < NB) {
        int li = base + tid; if (li >= N_SEL) li = N_SEL - 1;
        int node = g_list[li];
        unsigned long long key = g_win[node];
        int gid = __ldg(&n_id[node]);
        int lu  = __ldg(&last_update[gid]);
        bool valid = (key != 0ull);
        int dst = 0, tt = 0; const float* raw = raw_s; float trel = 0.f;
        if (valid) {
            int e = (int)(key & 0xffffffffull);
            tt = (int)(key >> 32) - 1;
            if (e < EVN) { dst = __ldg(&dst_s[e]); raw = raw_s + (size_t)e * RAWD; }
            else { int e2 = e - EVN; dst = __ldg(&dst_d[e2]); raw = raw_d + (size_t)e2 * RAWD; }
            trel = (float)(tt - lu);
        }
        s_idx[tid] = node; s_gid[tid] = gid; s_dst[tid] = dst;
        s_raw[tid] = raw; s_trel[tid] = trel; s_val[tid] = valid ? 1 : 0;
        if (write_lu && base + tid < N_SEL)
            out_lu[node] = (float)(valid ? max(lu, tt) : lu);
    }
    __syncthreads();

    float acc[2][13][4];
    #pragma unroll
    for (int i = 0; i < 2; i++)
        #pragma unroll
        for (int j = 0; j < 13; j++)
            #pragma unroll
            for (int k = 0; k < 4; k++) acc[i][j][k] = 0.f;

    // all-invalid blocks: only chunks covering h cols [472,572) -> kc 7,8
    const int kc_start = (base < nValid) ? 0 : 7;

    // ---- pipeline prologue: A(kc0), B(kc0), B(kc0+1) ----
    stage_a(smem, kc_start, kc_start & 1, tid, memory, time_w, time_b,
            s_gid, s_dst, s_raw, s_trel, s_val);
    stage_b(sm32, kc_start, kc_start % 3, tid);
    CP_COMMIT();
    stage_b(sm32, kc_start + 1, (kc_start + 1) % 3, tid);   // kc_start+1 <= 8 always
    CP_COMMIT();

    // ---- mainloop: ONE barrier per chunk; stage after compute ----
    for (int kc = kc_start; kc < KCH; kc++) {
        CP_WAIT1();          // all groups except newest done -> B(kc) resident
        __syncthreads();     // A(kc) STS + B(kc) smem visible; protects buffer reuse
        compute_chunk(smem, kc & 1, kc % 3, wm, wn, g, t, acc);
        if (kc + 1 < KCH)
            stage_a(smem, kc + 1, (kc + 1) & 1, tid, memory, time_w, time_b,
                    s_gid, s_dst, s_raw, s_trel, s_val);
        if (kc + 2 < KCH)
            stage_b(sm32, kc + 2, (kc + 2) % 3, tid);
        CP_COMMIT();         // one commit per iteration (possibly empty) keeps count invariant
    }
    __syncthreads();         // compute(8) done before epilogue reuses smem

    // ---- epilogue: two 64-row passes through smem, GRU gates, write out ----
    float* Dp = (float*)smem;                 // 64 x 404 f32, reuses A/B buffers
    #pragma unroll
    for (int p = 0; p < 2; p++) {
        if ((wm >> 1) == p) {
            #pragma unroll
            for (int mt = 0; mt < 2; mt++) {
                int r0 = (wm & 1) * 32 + mt * 16 + g;
                #pragma unroll
                for (int nt = 0; nt < 13; nt++) {
                    int c = wn * 100 + nt * 8 + 2 * t;
                    Dp[r0 * 404 + c]           = acc[mt][nt][0];
                    Dp[r0 * 404 + c + 1]       = acc[mt][nt][1];
                    Dp[(r0 + 8) * 404 + c]     = acc[mt][nt][2];
                    Dp[(r0 + 8) * 404 + c + 1] = acc[mt][nt][3];
                }
            }
        }
        __syncthreads();
        for (int idx = tid; idx < 64 * MEMD; idx += NTHR) {
            int ml = idx / MEMD, c = idx - ml * MEMD;
            int m = p * 64 + ml;
            float r = Dp[ml * 404 + c]       + __ldg(&b_ih[c])       + __ldg(&b_hh[c]);
            float z = Dp[ml * 404 + 100 + c] + __ldg(&b_ih[100 + c]) + __ldg(&b_hh[100 + c]);
            r = 1.f / (1.f + expf(-r));
            z = 1.f / (1.f + expf(-z));
            float hn = Dp[ml * 404 + 300 + c] + __ldg(&b_hh[200 + c]);
            float n = tanhf(Dp[ml * 404 + 200 + c] + __ldg(&b_ih[200 + c]) + r * hn);
            float h = __ldg(memory + (size_t)s_gid[m] * MEMD + c);
            out_mem[(size_t)s_idx[m] * MEMD + c] = fmaf(z, h - n, n);
        }
        __syncthreads();
    }
}

// ---------------- launch ----------------
extern "C" void kernel_launch(void* const* d_in, const int* in_sizes, int n_in,
                              void* d_out, int out_size) {
    const float* memory      = (const float*)d_in[0];
    const int*   last_update = (const int*)  d_in[1];
    const int*   n_id        = (const int*)  d_in[2];
    const int*   loc_s       = (const int*)  d_in[3];
    const int*   dst_s       = (const int*)  d_in[4];
    const int*   t_s         = (const int*)  d_in[5];
    const float* raw_s       = (const float*)d_in[6];
    const int*   loc_d       = (const int*)  d_in[7];
    const int*   dst_d       = (const int*)  d_in[8];
    const int*   t_d         = (const int*)  d_in[9];
    const float* raw_d       = (const float*)d_in[10];
    const float* time_w      = (const float*)d_in[11];
    const float* time_b      = (const float*)d_in[12];
    const float* W_ih        = (const float*)d_in[13];
    const float* W_hh        = (const float*)d_in[14];
    const float* b_ih        = (const float*)d_in[15];
    const float* b_hh        = (const float*)d_in[16];

    float* out_mem = (float*)d_out;
    float* out_lu  = out_mem + (size_t)N_SEL * MEMD;
    int write_lu = (out_size >= N_SEL * MEMD + N_SEL) ? 1 : 0;

    cudaFuncSetAttribute(k_main3, cudaFuncAttributeMaxDynamicSharedMemorySize, SMEM_TOTAL);

    k_init     <<<(N_SEL + 255) / 256, 256>>>();
    k_aggregate<<<(2 * EVN + 255) / 256, 256>>>(loc_s, t_s, loc_d, t_d);
    k_partition<<<(N_SEL + 255) / 256, 256>>>();
    k_prepack  <<<(BROWS * 288 + 255) / 256, 256>>>(W_ih, W_hh);
    k_main3    <<<NBLK, NTHR, SMEM_TOTAL>>>(memory, last_update, n_id,
                                            dst_s, raw_s, dst_d, raw_d,
                                            time_w, time_b, b_ih, b_hh,
                                            out_mem, out_lu, write_lu);
}